// round 11
// baseline (speedup 1.0000x reference)
#include <cuda_runtime.h>
#include <cuda_bf16.h>
#include <cstdint>

// out[b] = ||x_b||^2 * (x_b^T S x_b),  S=(rho+rho^T)/2, x=h+l, S=Sh+Sl:
//   q ~= h^T Sh (h + 2l) + h^T Sl h     (2-term; dropped O(eps^2))
// R11 = R10 (K-split across 2 CTAs, 2 CTAs/SM) with B_PITCH fixed to 80B
// (16B-aligned for cp.async/ldmatrix; R10's 72B pitch caused the fault).

#define BATCH 4096
#define DIMX 256
#define TILE_M 32
#define NTHREADS 256
#define KHALF 128
#define NKCHUNKS 4          // chunks of 32 cols within this CTA's K-half

__device__ __nv_bfloat16 g_Sh[DIMX * DIMX];
__device__ __nv_bfloat16 g_Sl[DIMX * DIMX];
__device__ float g_q[BATCH];
__device__ int   g_cnt[BATCH / TILE_M];

// ---- dynamic smem (bytes) ----
#define A_STRIDE 264        // bf16/row (528B pitch; ldsm conflict-free)
#define B_PITCH  80         // bytes/row: 64B data + 16B pad (16B-aligned!)
#define SM_AH    0                      // 32 x 528 = 16896
#define SM_AL    16896                  // -> 33792
#define SM_BH0   33792                  // 256 x 80 = 20480 -> 54272
#define SM_BL0   54272                  // -> 74752
#define SM_BH1   74752                  // -> 95232
#define SM_BL1   95232                  // -> 115712
// QP/NP/flag alias stage-0 B (dead after epilogue syncthreads)
#define SM_QP    33792                  // float[8][32] = 1024
#define SM_NP    34816                  // float[8][32] = 1024
#define SM_FLAG  35840
#define SMEM_TOTAL 115712

__device__ __forceinline__ uint32_t smem_u32(const void* p) {
    uint32_t a;
    asm("{ .reg .u64 t; cvta.to.shared.u64 t, %1; cvt.u32.u64 %0, t; }"
        : "=r"(a) : "l"(p));
    return a;
}
__device__ __forceinline__ void cp16(uint32_t dst, const void* src) {
    asm volatile("cp.async.cg.shared.global [%0], [%1], 16;" :: "r"(dst), "l"(src));
}
__device__ __forceinline__ void cp_commit() {
    asm volatile("cp.async.commit_group;" ::: "memory");
}
__device__ __forceinline__ void mma16816(float* c, const uint32_t* a, const uint32_t* b) {
    asm volatile(
        "mma.sync.aligned.m16n8k16.row.col.f32.bf16.bf16.f32 "
        "{%0,%1,%2,%3}, {%4,%5,%6,%7}, {%8,%9}, {%0,%1,%2,%3};"
        : "+f"(c[0]), "+f"(c[1]), "+f"(c[2]), "+f"(c[3])
        : "r"(a[0]), "r"(a[1]), "r"(a[2]), "r"(a[3]), "r"(b[0]), "r"(b[1]));
}
__device__ __forceinline__ void ldsm_x4(uint32_t* r, uint32_t addr) {
    asm volatile("ldmatrix.sync.aligned.m8n8.x4.shared.b16 {%0,%1,%2,%3}, [%4];"
                 : "=r"(r[0]), "=r"(r[1]), "=r"(r[2]), "=r"(r[3]) : "r"(addr));
}
__device__ __forceinline__ void split4(const float4 v, uint2& hi, uint2& lo) {
    __nv_bfloat162 h01 = __float22bfloat162_rn(make_float2(v.x, v.y));
    __nv_bfloat162 h23 = __float22bfloat162_rn(make_float2(v.z, v.w));
    float2 f01 = __bfloat1622float2(h01);
    float2 f23 = __bfloat1622float2(h23);
    __nv_bfloat162 l01 = __float22bfloat162_rn(make_float2(v.x - f01.x, v.y - f01.y));
    __nv_bfloat162 l23 = __float22bfloat162_rn(make_float2(v.z - f23.x, v.w - f23.y));
    hi.x = *reinterpret_cast<const uint32_t*>(&h01);
    hi.y = *reinterpret_cast<const uint32_t*>(&h23);
    lo.x = *reinterpret_cast<const uint32_t*>(&l01);
    lo.y = *reinterpret_cast<const uint32_t*>(&l23);
}

// ---- cvt: S = (rho + rho^T)/2 via smem tile transpose, split bf16 hi/lo ----
__global__ void cvt_sym(const float* __restrict__ R) {
    __shared__ float tB[32][33];
    const int ti = blockIdx.x >> 3, tj = blockIdx.x & 7;
    const int tx = threadIdx.x & 31, ty = threadIdx.x >> 5;   // 32 x 8
    #pragma unroll
    for (int i = 0; i < 4; i++)
        tB[ty + i * 8][tx] = R[(size_t)(tj * 32 + ty + i * 8) * DIMX + ti * 32 + tx];
    __syncthreads();
    #pragma unroll
    for (int i = 0; i < 4; i++) {
        const int r = ti * 32 + ty + i * 8, c = tj * 32 + tx;
        const float s = 0.5f * (R[(size_t)r * DIMX + c] + tB[tx][ty + i * 8]);
        const __nv_bfloat16 h = __float2bfloat16(s);
        const __nv_bfloat16 l = __float2bfloat16(s - __bfloat162float(h));
        g_Sh[(size_t)r * DIMX + c] = h;
        g_Sl[(size_t)r * DIMX + c] = l;
    }
}

__global__ __launch_bounds__(NTHREADS, 2)
void qmd_mma(const float* __restrict__ X, float* __restrict__ out) {
    extern __shared__ char smem[];
    const uint32_t sb = smem_u32(smem);
    const int t = threadIdx.x;
    const int wid = t >> 5;
    const int lane = t & 31;

    const int mt = blockIdx.x >> 1;      // M tile 0..127
    const int kh = blockIdx.x & 1;       // K half 0..1
    const int b0 = mt * TILE_M;
    const int k0 = kh * KHALF;

    const int n_base = wid * 32;         // warp's 32-col N slice

    // ---- prefetch B chunks 0,1 ----
    #pragma unroll
    for (int kb = 0; kb < 2; kb++) {
        const uint32_t bh = kb ? SM_BH1 : SM_BH0;
        const uint32_t bl = kb ? SM_BL1 : SM_BL0;
        #pragma unroll
        for (int i = 0; i < 8; i++) {
            const int f = t + i * NTHREADS;           // 0..2047
            const int arr = f >> 10, rem = f & 1023;
            const int n = rem >> 2, c = rem & 3;      // 256 rows x 4 (16B units)
            const uint32_t dst = sb + (arr ? bl : bh) + n * B_PITCH + c * 16;
            const __nv_bfloat16* src = (arr ? g_Sl : g_Sh)
                                       + (size_t)n * DIMX + k0 + kb * 32 + c * 8;
            cp16(dst, src);
        }
        cp_commit();
    }

    // ---- load + convert A tile (full K kept for epilogue dot products) ----
    {
        const float4* __restrict__ Xg = reinterpret_cast<const float4*>(X);
        #pragma unroll
        for (int i = 0; i < 8; i++) {
            const int f = t + i * NTHREADS;           // 0..2047
            const int r = f >> 6, c4 = f & 63;
            float4 v = Xg[(size_t)(b0 + r) * (DIMX / 4) + c4];
            uint2 hi, lo;
            split4(v, hi, lo);
            const uint32_t off = r * (A_STRIDE * 2) + c4 * 8;
            *reinterpret_cast<uint2*>(smem + SM_AH + off) = hi;
            *reinterpret_cast<uint2*>(smem + SM_AL + off) = lo;
        }
    }

    float acc_a[2][4][4], acc_b[2][4][4];
    #pragma unroll
    for (int mi = 0; mi < 2; mi++)
        #pragma unroll
        for (int ni = 0; ni < 4; ni++)
            #pragma unroll
            for (int e = 0; e < 4; e++) { acc_a[mi][ni][e] = 0.0f; acc_b[mi][ni][e] = 0.0f; }

    const int m_idx = lane >> 3;
    const uint32_t a_rowoff = ((m_idx & 1) * 8 + (lane & 7)) * (A_STRIDE * 2)
                              + (m_idx >> 1) * 16;
    const uint32_t b_part = (m_idx >> 1) * 8 + (lane & 7);
    const uint32_t b_off0 = (n_base + b_part) * B_PITCH + (m_idx & 1) * 16;
    const uint32_t b_off1 = (n_base + 16 + b_part) * B_PITCH + (m_idx & 1) * 16;

    for (int kb = 0; kb < NKCHUNKS; kb++) {
        if (kb == NKCHUNKS - 1)
            asm volatile("cp.async.wait_group 0;" ::: "memory");
        else
            asm volatile("cp.async.wait_group 1;" ::: "memory");
        __syncthreads();

        const uint32_t bh = sb + ((kb & 1) ? SM_BH1 : SM_BH0);
        const uint32_t bl = sb + ((kb & 1) ? SM_BL1 : SM_BL0);

        #pragma unroll
        for (int k16 = 0; k16 < 2; k16++) {
            const int kcA = k0 + kb * 32 + k16 * 16;
            const uint32_t kob = k16 * 32;            // chunk-local byte offset

            uint32_t aH[2][4], bHf[8], bLf[8];
            #pragma unroll
            for (int mi = 0; mi < 2; mi++)
                ldsm_x4(aH[mi], sb + SM_AH + mi * 16 * (A_STRIDE * 2)
                                   + a_rowoff + kcA * 2);
            ldsm_x4(&bHf[0], bh + b_off0 + kob);
            ldsm_x4(&bHf[4], bh + b_off1 + kob);
            ldsm_x4(&bLf[0], bl + b_off0 + kob);
            ldsm_x4(&bLf[4], bl + b_off1 + kob);

            #pragma unroll
            for (int mi = 0; mi < 2; mi++)
                #pragma unroll
                for (int ni = 0; ni < 4; ni++) {
                    mma16816(acc_a[mi][ni], aH[mi], &bHf[ni * 2]);  // h^T Sh
                    mma16816(acc_b[mi][ni], aH[mi], &bLf[ni * 2]);  // h^T Sl
                }
        }
        __syncthreads();

        if (kb < NKCHUNKS - 2) {
            const int nk = kb + 2;
            const uint32_t dbh = (kb & 1) ? SM_BH1 : SM_BH0;
            const uint32_t dbl = (kb & 1) ? SM_BL1 : SM_BL0;
            #pragma unroll
            for (int i = 0; i < 8; i++) {
                const int f = t + i * NTHREADS;
                const int arr = f >> 10, rem = f & 1023;
                const int n = rem >> 2, c = rem & 3;
                const uint32_t dst = sb + (arr ? dbl : dbh) + n * B_PITCH + c * 16;
                const __nv_bfloat16* src = (arr ? g_Sl : g_Sh)
                                           + (size_t)n * DIMX + k0 + nk * 32 + c * 8;
                cp16(dst, src);
            }
            cp_commit();
        }
    }

    // ---- epilogue: q_part = sum_j Za*(h+2l)_j + Zb*h_j ;  n = sum_j (h+l)^2 ----
    const __nv_bfloat16* sAh = reinterpret_cast<const __nv_bfloat16*>(smem + SM_AH);
    const __nv_bfloat16* sAl = reinterpret_cast<const __nv_bfloat16*>(smem + SM_AL);
    float q[4] = {0, 0, 0, 0};
    float nn[4] = {0, 0, 0, 0};
    #pragma unroll
    for (int mi = 0; mi < 2; mi++) {
        #pragma unroll
        for (int ni = 0; ni < 4; ni++) {
            const int j0 = n_base + ni * 8 + (lane & 3) * 2;
            const int r0 = mi * 16 + (lane >> 2);
            #pragma unroll
            for (int e = 0; e < 4; e++) {
                const int r = r0 + (e >> 1) * 8;
                const int j = j0 + (e & 1);
                const float xh = __bfloat162float(sAh[r * A_STRIDE + j]);
                const float xl = __bfloat162float(sAl[r * A_STRIDE + j]);
                const int s = mi * 2 + (e >> 1);
                q[s] = fmaf(acc_a[mi][ni][e], xh + 2.0f * xl, q[s]);
                q[s] = fmaf(acc_b[mi][ni][e], xh, q[s]);
                const float xf = xh + xl;
                nn[s] = fmaf(xf, xf, nn[s]);
            }
        }
    }
    #pragma unroll
    for (int off = 1; off <= 2; off <<= 1) {
        #pragma unroll
        for (int s = 0; s < 4; s++) {
            q[s] += __shfl_xor_sync(0xffffffffu, q[s], off);
            nn[s] += __shfl_xor_sync(0xffffffffu, nn[s], off);
        }
    }
    __syncthreads();                    // stage-0 B dead -> safe to alias QP/NP
    float* qp = reinterpret_cast<float*>(smem + SM_QP);
    float* np = reinterpret_cast<float*>(smem + SM_NP);
    if ((lane & 3) == 0) {
        #pragma unroll
        for (int s = 0; s < 4; s++) {
            const int r = (s >> 1) * 16 + (lane >> 2) + (s & 1) * 8;
            qp[wid * 32 + r] = q[s];
            np[wid * 32 + r] = nn[s];
        }
    }
    __syncthreads();

    // ---- cross-CTA K-combine (R8-validated protocol) ----
    if (t < TILE_M) {
        float qs = 0.0f;
        #pragma unroll
        for (int w = 0; w < 8; w++) qs += qp[w * 32 + t];
        atomicAdd(&g_q[b0 + t], qs);
    }
    __threadfence();
    __syncthreads();

    int* flag = reinterpret_cast<int*>(smem + SM_FLAG);
    if (t == 0) {
        const int old = atomicAdd(&g_cnt[mt], 1);
        *flag = (old == 1);
    }
    __syncthreads();

    if (*flag) {                         // second arriver finalizes
        __threadfence();
        if (t < TILE_M) {
            float ns = 0.0f;
            #pragma unroll
            for (int w = 0; w < 8; w++) ns += np[w * 32 + t];
            const float qq = *reinterpret_cast<volatile float*>(&g_q[b0 + t]);
            out[b0 + t] = qq * ns;
            g_q[b0 + t] = 0.0f;          // reset for next replay
        }
        if (t == 0) g_cnt[mt] = 0;
    }
}

extern "C" void kernel_launch(void* const* d_in, const int* in_sizes, int n_in,
                              void* d_out, int out_size) {
    const float* X   = (const float*)d_in[0];
    const float* rho = (const float*)d_in[1];
    float* out = (float*)d_out;

    cvt_sym<<<64, 256>>>(rho);

    cudaFuncSetAttribute(qmd_mma, cudaFuncAttributeMaxDynamicSharedMemorySize, SMEM_TOTAL);
    qmd_mma<<<(out_size / TILE_M) * 2, NTHREADS, SMEM_TOTAL>>>(X, out);
}

// round 12
// speedup vs baseline: 1.6290x; 1.6290x over previous
#include <cuda_runtime.h>
#include <cuda_bf16.h>
#include <cstdint>

// out[b] = ||x_b||^2 * (x_b^T S x_b),  S=(rho+rho^T)/2, x=h+l, S=Sh+Sl:
//   q ~= h^T Sh (h + 2l) + h^T Sl h      (2-term; dropped O(eps^2))
// R12 = R9 (best) with the B path converted from 8192 cp.async (rt=8cyc each)
// to 8 cp.async.bulk chunk copies + mbarrier. cvt_sym pre-packs Sh/Sl into
// chunk-major, XOR-swizzled gmem so each 32KB chunk is one contiguous copy.

#define BATCH 4096
#define DIMX 256
#define TILE_M 32
#define NTHREADS 512
#define NKCHUNKS 4            // K chunks of 64 cols
#define CHUNK_BYTES 32768     // 256 rows x 128 bytes

// chunk-major, swizzled: byte(r,c) = (c>>6)*32768 + r*128 + ((2*(c&63)) ^ ((r&7)<<4))
__device__ __nv_bfloat16 g_Sh[DIMX * DIMX];
__device__ __nv_bfloat16 g_Sl[DIMX * DIMX];

// ---- dynamic smem (bytes) ----
#define A_STRIDE 264          // bf16/row (528B pitch; ldsm conflict-free)
#define SM_AH    0                      // 32 x 528 = 16896
#define SM_AL    16896                  // -> 33792
#define SM_BH0   33792                  // 32768 -> 66560
#define SM_BL0   66560                  // -> 99328
#define SM_BH1   99328                  // -> 132096
#define SM_BL1   132096                 // -> 164864
#define SM_QP    164864                 // float[16][32] = 2048
#define SM_NP    166912                 // float[16][32] = 2048
#define SM_MB    168960                 // 2 x 8B mbarriers
#define SMEM_TOTAL 169088

__device__ __forceinline__ uint32_t smem_u32(const void* p) {
    uint32_t a;
    asm("{ .reg .u64 t; cvta.to.shared.u64 t, %1; cvt.u32.u64 %0, t; }"
        : "=r"(a) : "l"(p));
    return a;
}
__device__ __forceinline__ void mbar_init(uint32_t addr, uint32_t cnt) {
    asm volatile("mbarrier.init.shared.b64 [%0], %1;" :: "r"(addr), "r"(cnt) : "memory");
}
__device__ __forceinline__ void mbar_expect_tx(uint32_t addr, uint32_t bytes) {
    asm volatile("mbarrier.arrive.expect_tx.shared.b64 _, [%0], %1;"
                 :: "r"(addr), "r"(bytes) : "memory");
}
__device__ __forceinline__ void mbar_wait(uint32_t addr, uint32_t parity) {
    asm volatile(
        "{\n\t.reg .pred P;\n\t"
        "WL_%=:\n\t"
        "mbarrier.try_wait.parity.acquire.cta.shared::cta.b64 P, [%0], %1, 0x989680;\n\t"
        "@P bra.uni WD_%=;\n\t"
        "bra.uni WL_%=;\n\t"
        "WD_%=:\n\t}"
        :: "r"(addr), "r"(parity) : "memory");
}
__device__ __forceinline__ void bulk_g2s(uint32_t dst, const void* src,
                                         uint32_t bytes, uint32_t mbar) {
    asm volatile(
        "cp.async.bulk.shared::cta.global.mbarrier::complete_tx::bytes "
        "[%0], [%1], %2, [%3];"
        :: "r"(dst), "l"(src), "r"(bytes), "r"(mbar) : "memory");
}
__device__ __forceinline__ void mma16816(float* c, const uint32_t* a, const uint32_t* b) {
    asm volatile(
        "mma.sync.aligned.m16n8k16.row.col.f32.bf16.bf16.f32 "
        "{%0,%1,%2,%3}, {%4,%5,%6,%7}, {%8,%9}, {%0,%1,%2,%3};"
        : "+f"(c[0]), "+f"(c[1]), "+f"(c[2]), "+f"(c[3])
        : "r"(a[0]), "r"(a[1]), "r"(a[2]), "r"(a[3]), "r"(b[0]), "r"(b[1]));
}
__device__ __forceinline__ void ldsm_x4(uint32_t* r, uint32_t addr) {
    asm volatile("ldmatrix.sync.aligned.m8n8.x4.shared.b16 {%0,%1,%2,%3}, [%4];"
                 : "=r"(r[0]), "=r"(r[1]), "=r"(r[2]), "=r"(r[3]) : "r"(addr));
}
__device__ __forceinline__ void ldsm_x2(uint32_t* r, uint32_t addr) {
    asm volatile("ldmatrix.sync.aligned.m8n8.x2.shared.b16 {%0,%1}, [%2];"
                 : "=r"(r[0]), "=r"(r[1]) : "r"(addr));
}
__device__ __forceinline__ void split4(const float4 v, uint2& hi, uint2& lo) {
    __nv_bfloat162 h01 = __float22bfloat162_rn(make_float2(v.x, v.y));
    __nv_bfloat162 h23 = __float22bfloat162_rn(make_float2(v.z, v.w));
    float2 f01 = __bfloat1622float2(h01);
    float2 f23 = __bfloat1622float2(h23);
    __nv_bfloat162 l01 = __float22bfloat162_rn(make_float2(v.x - f01.x, v.y - f01.y));
    __nv_bfloat162 l23 = __float22bfloat162_rn(make_float2(v.z - f23.x, v.w - f23.y));
    hi.x = *reinterpret_cast<const uint32_t*>(&h01);
    hi.y = *reinterpret_cast<const uint32_t*>(&h23);
    lo.x = *reinterpret_cast<const uint32_t*>(&l01);
    lo.y = *reinterpret_cast<const uint32_t*>(&l23);
}

// ---- cvt: S=(rho+rho^T)/2, bf16 hi/lo, packed chunk-major + swizzled ----
__global__ void cvt_sym(const float* __restrict__ R) {
    __shared__ float tB[32][33];
    const int ti = blockIdx.x >> 3, tj = blockIdx.x & 7;
    const int tx = threadIdx.x & 31, ty = threadIdx.x >> 5;   // 32 x 8
    #pragma unroll
    for (int i = 0; i < 4; i++)
        tB[ty + i * 8][tx] = R[(size_t)(tj * 32 + ty + i * 8) * DIMX + ti * 32 + tx];
    __syncthreads();
    char* dsh = reinterpret_cast<char*>(g_Sh);
    char* dsl = reinterpret_cast<char*>(g_Sl);
    #pragma unroll
    for (int i = 0; i < 4; i++) {
        const int r = ti * 32 + ty + i * 8, c = tj * 32 + tx;
        const float s = 0.5f * (R[(size_t)r * DIMX + c] + tB[tx][ty + i * 8]);
        const __nv_bfloat16 h = __float2bfloat16(s);
        const __nv_bfloat16 l = __float2bfloat16(s - __bfloat162float(h));
        const uint32_t byte = (uint32_t)(c >> 6) * CHUNK_BYTES + r * 128
                              + (((c & 63) * 2) ^ ((r & 7) << 4));
        *reinterpret_cast<__nv_bfloat16*>(dsh + byte) = h;
        *reinterpret_cast<__nv_bfloat16*>(dsl + byte) = l;
    }
}

__global__ __launch_bounds__(NTHREADS, 1)
void qmd_mma(const float* __restrict__ X, float* __restrict__ out) {
    extern __shared__ char smem[];
    const uint32_t sb = smem_u32(smem);
    const int t = threadIdx.x;
    const int wid = t >> 5;
    const int lane = t & 31;
    const int b0 = blockIdx.x * TILE_M;

    const char* srch = reinterpret_cast<const char*>(g_Sh);
    const char* srcl = reinterpret_cast<const char*>(g_Sl);

    // ---- mbarrier init + arm stages 0,1 with bulk copies ----
    if (t == 0) { mbar_init(sb + SM_MB, 1); mbar_init(sb + SM_MB + 8, 1); }
    __syncthreads();
    if (t == 0) {
        mbar_expect_tx(sb + SM_MB, 2 * CHUNK_BYTES);
        bulk_g2s(sb + SM_BH0, srch, CHUNK_BYTES, sb + SM_MB);
        bulk_g2s(sb + SM_BL0, srcl, CHUNK_BYTES, sb + SM_MB);
        mbar_expect_tx(sb + SM_MB + 8, 2 * CHUNK_BYTES);
        bulk_g2s(sb + SM_BH1, srch + CHUNK_BYTES, CHUNK_BYTES, sb + SM_MB + 8);
        bulk_g2s(sb + SM_BL1, srcl + CHUNK_BYTES, CHUNK_BYTES, sb + SM_MB + 8);
    }

    // ---- load + convert A tile (overlaps bulk copies) ----
    {
        const float4* __restrict__ Xg = reinterpret_cast<const float4*>(X);
        #pragma unroll
        for (int i = 0; i < 4; i++) {
            const int f = t + i * NTHREADS;           // 0..2047
            const int r = f >> 6, c4 = f & 63;
            float4 v = Xg[(size_t)(b0 + r) * (DIMX / 4) + c4];
            uint2 hi, lo;
            split4(v, hi, lo);
            const uint32_t off = r * (A_STRIDE * 2) + c4 * 8;
            *reinterpret_cast<uint2*>(smem + SM_AH + off) = hi;
            *reinterpret_cast<uint2*>(smem + SM_AL + off) = lo;
        }
    }
    __syncthreads();                                  // A tile visible to all

    float acc_a[2][2][4], acc_b[2][2][4];
    #pragma unroll
    for (int mi = 0; mi < 2; mi++)
        #pragma unroll
        for (int ni = 0; ni < 2; ni++)
            #pragma unroll
            for (int e = 0; e < 4; e++) { acc_a[mi][ni][e] = 0.0f; acc_b[mi][ni][e] = 0.0f; }

    const int n_base = wid * 16;                      // warp's 16-col N slice
    // A ldsm addressing (R9 layout, padded pitch)
    const int m_idx = lane >> 3;
    const uint32_t a_rowoff = ((m_idx & 1) * 8 + (lane & 7)) * (A_STRIDE * 2)
                              + (m_idx >> 1) * 16;
    // B ldsm addressing (swizzled 128B pitch). x2 uses lanes 0-15.
    const int l2 = lane & 15;
    const uint32_t b_row0 = (uint32_t)(n_base + (l2 & 7)) * 128;  // ni adds 1024
    const uint32_t b_rsw  = (uint32_t)(l2 & 7) << 4;
    const uint32_t b_kpart = (uint32_t)(l2 >> 3) * 16;

    for (int kb = 0; kb < NKCHUNKS; kb++) {
        mbar_wait(sb + SM_MB + 8 * (kb & 1), (kb >> 1) & 1);

        const uint32_t bh = sb + ((kb & 1) ? SM_BH1 : SM_BH0);
        const uint32_t bl = sb + ((kb & 1) ? SM_BL1 : SM_BL0);

        #pragma unroll
        for (int k16 = 0; k16 < 4; k16++) {
            const int kcA = kb * 64 + k16 * 16;
            const uint32_t kloc = (uint32_t)k16 * 32 + b_kpart;
            const uint32_t kcol = kloc ^ b_rsw;       // swizzled col byte

            uint32_t aH[2][4];
            #pragma unroll
            for (int mi = 0; mi < 2; mi++)
                ldsm_x4(aH[mi], sb + SM_AH + mi * 16 * (A_STRIDE * 2)
                                   + a_rowoff + kcA * 2);

            uint32_t bHf[2][2], bLf[2][2];
            #pragma unroll
            for (int ni = 0; ni < 2; ni++) {
                const uint32_t bo = b_row0 + ni * 1024 + kcol;
                ldsm_x2(bHf[ni], bh + bo);
                ldsm_x2(bLf[ni], bl + bo);
            }
            #pragma unroll
            for (int mi = 0; mi < 2; mi++)
                #pragma unroll
                for (int ni = 0; ni < 2; ni++) {
                    mma16816(acc_a[mi][ni], aH[mi], bHf[ni]);   // h^T Sh
                    mma16816(acc_b[mi][ni], aH[mi], bLf[ni]);   // h^T Sl
                }
        }
        __syncthreads();                              // all done with this stage

        if (kb < NKCHUNKS - 2) {                      // re-arm + bulk chunk kb+2
            if (t == 0) {
                const int nk = kb + 2;
                const uint32_t mb = sb + SM_MB + 8 * (kb & 1);
                mbar_expect_tx(mb, 2 * CHUNK_BYTES);
                bulk_g2s((kb & 1) ? sb + SM_BH1 : sb + SM_BH0,
                         srch + (size_t)nk * CHUNK_BYTES, CHUNK_BYTES, mb);
                bulk_g2s((kb & 1) ? sb + SM_BL1 : sb + SM_BL0,
                         srcl + (size_t)nk * CHUNK_BYTES, CHUNK_BYTES, mb);
            }
        }
    }

    // ---- fused epilogue: q = sum_j Za*(h+2l) + Zb*h ;  n = sum_j (h+l)^2 ----
    const __nv_bfloat16* sAh = reinterpret_cast<const __nv_bfloat16*>(smem + SM_AH);
    const __nv_bfloat16* sAl = reinterpret_cast<const __nv_bfloat16*>(smem + SM_AL);
    float q[4] = {0, 0, 0, 0};
    float nn[4] = {0, 0, 0, 0};
    #pragma unroll
    for (int mi = 0; mi < 2; mi++) {
        #pragma unroll
        for (int ni = 0; ni < 2; ni++) {
            const int j0 = n_base + ni * 8 + (lane & 3) * 2;
            const int r0 = mi * 16 + (lane >> 2);
            #pragma unroll
            for (int e = 0; e < 4; e++) {
                const int r = r0 + (e >> 1) * 8;
                const int j = j0 + (e & 1);
                const float xh = __bfloat162float(sAh[r * A_STRIDE + j]);
                const float xl = __bfloat162float(sAl[r * A_STRIDE + j]);
                const int slot = mi * 2 + (e >> 1);
                q[slot] = fmaf(acc_a[mi][ni][e], xh + 2.0f * xl, q[slot]);
                q[slot] = fmaf(acc_b[mi][ni][e], xh, q[slot]);
                const float xf = xh + xl;
                nn[slot] = fmaf(xf, xf, nn[slot]);
            }
        }
    }
    #pragma unroll
    for (int off = 1; off <= 2; off <<= 1) {
        #pragma unroll
        for (int s = 0; s < 4; s++) {
            q[s] += __shfl_xor_sync(0xffffffffu, q[s], off);
            nn[s] += __shfl_xor_sync(0xffffffffu, nn[s], off);
        }
    }
    float* qp = reinterpret_cast<float*>(smem + SM_QP);
    float* np = reinterpret_cast<float*>(smem + SM_NP);
    if ((lane & 3) == 0) {
        #pragma unroll
        for (int s = 0; s < 4; s++) {
            const int r = (lane >> 2) + s * 8;
            qp[wid * 32 + r] = q[s];
            np[wid * 32 + r] = nn[s];
        }
    }
    __syncthreads();

    if (t < TILE_M) {
        float qq = 0.0f, ns = 0.0f;
        #pragma unroll
        for (int w = 0; w < 16; w++) {
            qq += qp[w * 32 + t];
            ns += np[w * 32 + t];
        }
        out[b0 + t] = qq * ns;
    }
}

extern "C" void kernel_launch(void* const* d_in, const int* in_sizes, int n_in,
                              void* d_out, int out_size) {
    const float* X   = (const float*)d_in[0];
    const float* rho = (const float*)d_in[1];
    float* out = (float*)d_out;

    cvt_sym<<<64, 256>>>(rho);

    cudaFuncSetAttribute(qmd_mma, cudaFuncAttributeMaxDynamicSharedMemorySize, SMEM_TOTAL);
    qmd_mma<<<out_size / TILE_M, NTHREADS, SMEM_TOTAL>>>(X, out);
}

// round 13
// speedup vs baseline: 1.9674x; 1.2077x over previous
#include <cuda_runtime.h>
#include <cuda_bf16.h>
#include <cstdint>

// out[b] = ||x_b||^2 * (x_b^T S x_b),  S=(rho+rho^T)/2, x=h+l, S=Sh+Sl:
//   q ~= h^T Sh (h + 2l) + h^T Sl h      (2-term; dropped O(eps^2))
// R13 = R12 with cvt fused into the main kernel. All 128 CTAs are resident
// (<=148 SMs), so a grid-wide ticket/spin handshake after the conversion
// phase is deadlock-free and replay-safe (monotonic epoch counter).

#define BATCH 4096
#define DIMX 256
#define TILE_M 32
#define NTHREADS 512
#define NKCHUNKS 4            // K chunks of 64 cols
#define CHUNK_BYTES 32768     // 256 rows x 128 bytes
#define NGRID (BATCH / TILE_M)   // 128

// chunk-major, swizzled: byte(r,c) = (c>>6)*32768 + r*128 + ((2*(c&63)) ^ ((r&7)<<4))
__device__ __nv_bfloat16 g_Sh[DIMX * DIMX];
__device__ __nv_bfloat16 g_Sl[DIMX * DIMX];
__device__ unsigned int g_cnt;   // monotonic across replays

// ---- dynamic smem (bytes) ----
#define A_STRIDE 264          // bf16/row (528B pitch; ldsm conflict-free)
#define SM_AH    0                      // 32 x 528 = 16896
#define SM_AL    16896                  // -> 33792
#define SM_BH0   33792                  // 32768 -> 66560
#define SM_BL0   66560                  // -> 99328
#define SM_BH1   99328                  // -> 132096
#define SM_BL1   132096                 // -> 164864
#define SM_QP    164864                 // float[16][32] = 2048
#define SM_NP    166912                 // float[16][32] = 2048
#define SM_MB    168960                 // 2 x 8B mbarriers
#define SMEM_TOTAL 169088

__device__ __forceinline__ uint32_t smem_u32(const void* p) {
    uint32_t a;
    asm("{ .reg .u64 t; cvta.to.shared.u64 t, %1; cvt.u32.u64 %0, t; }"
        : "=r"(a) : "l"(p));
    return a;
}
__device__ __forceinline__ void mbar_init(uint32_t addr, uint32_t cnt) {
    asm volatile("mbarrier.init.shared.b64 [%0], %1;" :: "r"(addr), "r"(cnt) : "memory");
}
__device__ __forceinline__ void mbar_expect_tx(uint32_t addr, uint32_t bytes) {
    asm volatile("mbarrier.arrive.expect_tx.shared.b64 _, [%0], %1;"
                 :: "r"(addr), "r"(bytes) : "memory");
}
__device__ __forceinline__ void mbar_wait(uint32_t addr, uint32_t parity) {
    asm volatile(
        "{\n\t.reg .pred P;\n\t"
        "WL_%=:\n\t"
        "mbarrier.try_wait.parity.acquire.cta.shared::cta.b64 P, [%0], %1, 0x989680;\n\t"
        "@P bra.uni WD_%=;\n\t"
        "bra.uni WL_%=;\n\t"
        "WD_%=:\n\t}"
        :: "r"(addr), "r"(parity) : "memory");
}
__device__ __forceinline__ void bulk_g2s(uint32_t dst, const void* src,
                                         uint32_t bytes, uint32_t mbar) {
    asm volatile(
        "cp.async.bulk.shared::cta.global.mbarrier::complete_tx::bytes "
        "[%0], [%1], %2, [%3];"
        :: "r"(dst), "l"(src), "r"(bytes), "r"(mbar) : "memory");
}
__device__ __forceinline__ void mma16816(float* c, const uint32_t* a, const uint32_t* b) {
    asm volatile(
        "mma.sync.aligned.m16n8k16.row.col.f32.bf16.bf16.f32 "
        "{%0,%1,%2,%3}, {%4,%5,%6,%7}, {%8,%9}, {%0,%1,%2,%3};"
        : "+f"(c[0]), "+f"(c[1]), "+f"(c[2]), "+f"(c[3])
        : "r"(a[0]), "r"(a[1]), "r"(a[2]), "r"(a[3]), "r"(b[0]), "r"(b[1]));
}
__device__ __forceinline__ void ldsm_x4(uint32_t* r, uint32_t addr) {
    asm volatile("ldmatrix.sync.aligned.m8n8.x4.shared.b16 {%0,%1,%2,%3}, [%4];"
                 : "=r"(r[0]), "=r"(r[1]), "=r"(r[2]), "=r"(r[3]) : "r"(addr));
}
__device__ __forceinline__ void ldsm_x2(uint32_t* r, uint32_t addr) {
    asm volatile("ldmatrix.sync.aligned.m8n8.x2.shared.b16 {%0,%1}, [%2];"
                 : "=r"(r[0]), "=r"(r[1]) : "r"(addr));
}
__device__ __forceinline__ void split4(const float4 v, uint2& hi, uint2& lo) {
    __nv_bfloat162 h01 = __float22bfloat162_rn(make_float2(v.x, v.y));
    __nv_bfloat162 h23 = __float22bfloat162_rn(make_float2(v.z, v.w));
    float2 f01 = __bfloat1622float2(h01);
    float2 f23 = __bfloat1622float2(h23);
    __nv_bfloat162 l01 = __float22bfloat162_rn(make_float2(v.x - f01.x, v.y - f01.y));
    __nv_bfloat162 l23 = __float22bfloat162_rn(make_float2(v.z - f23.x, v.w - f23.y));
    hi.x = *reinterpret_cast<const uint32_t*>(&h01);
    hi.y = *reinterpret_cast<const uint32_t*>(&h23);
    lo.x = *reinterpret_cast<const uint32_t*>(&l01);
    lo.y = *reinterpret_cast<const uint32_t*>(&l23);
}

__global__ __launch_bounds__(NTHREADS, 1)
void qmd_mma(const float* __restrict__ X, const float* __restrict__ R,
             float* __restrict__ out) {
    extern __shared__ char smem[];
    const uint32_t sb = smem_u32(smem);
    const int t = threadIdx.x;
    const int wid = t >> 5;
    const int lane = t & 31;
    const int b0 = blockIdx.x * TILE_M;

    if (t == 0) { mbar_init(sb + SM_MB, 1); mbar_init(sb + SM_MB + 8, 1); }

    // ---- phase 0: convert my 512 elements of S = (rho+rho^T)/2 ----
    {
        const int i = blockIdx.x * NTHREADS + t;    // 0..65535
        const int r = i >> 8, c = i & 255;
        const float s = 0.5f * (R[(size_t)r * DIMX + c] + R[(size_t)c * DIMX + r]);
        const __nv_bfloat16 h = __float2bfloat16(s);
        const __nv_bfloat16 l = __float2bfloat16(s - __bfloat162float(h));
        const uint32_t byte = (uint32_t)(c >> 6) * CHUNK_BYTES + r * 128
                              + (((c & 63) * 2) ^ ((r & 7) << 4));
        *reinterpret_cast<__nv_bfloat16*>(reinterpret_cast<char*>(g_Sh) + byte) = h;
        *reinterpret_cast<__nv_bfloat16*>(reinterpret_cast<char*>(g_Sl) + byte) = l;
    }

    // ---- phase 1: A tile load + split (independent of S; overlaps others) ----
    {
        const float4* __restrict__ Xg = reinterpret_cast<const float4*>(X);
        #pragma unroll
        for (int i = 0; i < 4; i++) {
            const int f = t + i * NTHREADS;           // 0..2047
            const int r = f >> 6, c4 = f & 63;
            float4 v = Xg[(size_t)(b0 + r) * (DIMX / 4) + c4];
            uint2 hi, lo;
            split4(v, hi, lo);
            const uint32_t off = r * (A_STRIDE * 2) + c4 * 8;
            *reinterpret_cast<uint2*>(smem + SM_AH + off) = hi;
            *reinterpret_cast<uint2*>(smem + SM_AL + off) = lo;
        }
    }
    __threadfence();                                  // S-writes globally visible
    __syncthreads();

    // ---- grid-wide handshake (replay-safe monotonic epoch counter) ----
    if (t == 0) {
        const unsigned int ticket = atomicAdd(&g_cnt, 1u);
        const unsigned int target = ((ticket >> 7) + 1u) << 7;   // next mult of 128
        while (true) {
            unsigned int v;
            asm volatile("ld.global.acquire.gpu.u32 %0, [%1];"
                         : "=r"(v) : "l"(&g_cnt));
            if (v >= target) break;
        }
        // arm + issue stages 0,1
        const char* srch = reinterpret_cast<const char*>(g_Sh);
        const char* srcl = reinterpret_cast<const char*>(g_Sl);
        mbar_expect_tx(sb + SM_MB, 2 * CHUNK_BYTES);
        bulk_g2s(sb + SM_BH0, srch, CHUNK_BYTES, sb + SM_MB);
        bulk_g2s(sb + SM_BL0, srcl, CHUNK_BYTES, sb + SM_MB);
        mbar_expect_tx(sb + SM_MB + 8, 2 * CHUNK_BYTES);
        bulk_g2s(sb + SM_BH1, srch + CHUNK_BYTES, CHUNK_BYTES, sb + SM_MB + 8);
        bulk_g2s(sb + SM_BL1, srcl + CHUNK_BYTES, CHUNK_BYTES, sb + SM_MB + 8);
    }

    float acc_a[2][2][4], acc_b[2][2][4];
    #pragma unroll
    for (int mi = 0; mi < 2; mi++)
        #pragma unroll
        for (int ni = 0; ni < 2; ni++)
            #pragma unroll
            for (int e = 0; e < 4; e++) { acc_a[mi][ni][e] = 0.0f; acc_b[mi][ni][e] = 0.0f; }

    const int n_base = wid * 16;                      // warp's 16-col N slice
    const int m_idx = lane >> 3;
    const uint32_t a_rowoff = ((m_idx & 1) * 8 + (lane & 7)) * (A_STRIDE * 2)
                              + (m_idx >> 1) * 16;
    const int l2 = lane & 15;
    const uint32_t b_row0 = (uint32_t)(n_base + (l2 & 7)) * 128;  // ni adds 1024
    const uint32_t b_rsw  = (uint32_t)(l2 & 7) << 4;
    const uint32_t b_kpart = (uint32_t)(l2 >> 3) * 16;

    for (int kb = 0; kb < NKCHUNKS; kb++) {
        mbar_wait(sb + SM_MB + 8 * (kb & 1), (kb >> 1) & 1);

        const uint32_t bh = sb + ((kb & 1) ? SM_BH1 : SM_BH0);
        const uint32_t bl = sb + ((kb & 1) ? SM_BL1 : SM_BL0);

        #pragma unroll
        for (int k16 = 0; k16 < 4; k16++) {
            const int kcA = kb * 64 + k16 * 16;
            const uint32_t kloc = (uint32_t)k16 * 32 + b_kpart;
            const uint32_t kcol = kloc ^ b_rsw;       // swizzled col byte

            uint32_t aH[2][4];
            #pragma unroll
            for (int mi = 0; mi < 2; mi++)
                ldsm_x4(aH[mi], sb + SM_AH + mi * 16 * (A_STRIDE * 2)
                                   + a_rowoff + kcA * 2);

            uint32_t bHf[2][2], bLf[2][2];
            #pragma unroll
            for (int ni = 0; ni < 2; ni++) {
                const uint32_t bo = b_row0 + ni * 1024 + kcol;
                ldsm_x2(bHf[ni], bh + bo);
                ldsm_x2(bLf[ni], bl + bo);
            }
            #pragma unroll
            for (int mi = 0; mi < 2; mi++)
                #pragma unroll
                for (int ni = 0; ni < 2; ni++) {
                    mma16816(acc_a[mi][ni], aH[mi], bHf[ni]);   // h^T Sh
                    mma16816(acc_b[mi][ni], aH[mi], bLf[ni]);   // h^T Sl
                }
        }
        __syncthreads();                              // stage consumed by all

        if (kb < NKCHUNKS - 2) {                      // re-arm + bulk chunk kb+2
            if (t == 0) {
                const int nk = kb + 2;
                const uint32_t mb = sb + SM_MB + 8 * (kb & 1);
                const char* srch = reinterpret_cast<const char*>(g_Sh);
                const char* srcl = reinterpret_cast<const char*>(g_Sl);
                mbar_expect_tx(mb, 2 * CHUNK_BYTES);
                bulk_g2s((kb & 1) ? sb + SM_BH1 : sb + SM_BH0,
                         srch + (size_t)nk * CHUNK_BYTES, CHUNK_BYTES, mb);
                bulk_g2s((kb & 1) ? sb + SM_BL1 : sb + SM_BL0,
                         srcl + (size_t)nk * CHUNK_BYTES, CHUNK_BYTES, mb);
            }
        }
    }

    // ---- fused epilogue: q = sum_j Za*(h+2l) + Zb*h ;  n = sum_j (h+l)^2 ----
    const __nv_bfloat16* sAh = reinterpret_cast<const __nv_bfloat16*>(smem + SM_AH);
    const __nv_bfloat16* sAl = reinterpret_cast<const __nv_bfloat16*>(smem + SM_AL);
    float q[4] = {0, 0, 0, 0};
    float nn[4] = {0, 0, 0, 0};
    #pragma unroll
    for (int mi = 0; mi < 2; mi++) {
        #pragma unroll
        for (int ni = 0; ni < 2; ni++) {
            const int j0 = n_base + ni * 8 + (lane & 3) * 2;
            const int r0 = mi * 16 + (lane >> 2);
            #pragma unroll
            for (int e = 0; e < 4; e++) {
                const int r = r0 + (e >> 1) * 8;
                const int j = j0 + (e & 1);
                const float xh = __bfloat162float(sAh[r * A_STRIDE + j]);
                const float xl = __bfloat162float(sAl[r * A_STRIDE + j]);
                const int slot = mi * 2 + (e >> 1);
                q[slot] = fmaf(acc_a[mi][ni][e], xh + 2.0f * xl, q[slot]);
                q[slot] = fmaf(acc_b[mi][ni][e], xh, q[slot]);
                const float xf = xh + xl;
                nn[slot] = fmaf(xf, xf, nn[slot]);
            }
        }
    }
    #pragma unroll
    for (int off = 1; off <= 2; off <<= 1) {
        #pragma unroll
        for (int s = 0; s < 4; s++) {
            q[s] += __shfl_xor_sync(0xffffffffu, q[s], off);
            nn[s] += __shfl_xor_sync(0xffffffffu, nn[s], off);
        }
    }
    float* qp = reinterpret_cast<float*>(smem + SM_QP);
    float* np = reinterpret_cast<float*>(smem + SM_NP);
    if ((lane & 3) == 0) {
        #pragma unroll
        for (int s = 0; s < 4; s++) {
            const int r = (lane >> 2) + s * 8;
            qp[wid * 32 + r] = q[s];
            np[wid * 32 + r] = nn[s];
        }
    }
    __syncthreads();

    if (t < TILE_M) {
        float qq = 0.0f, ns = 0.0f;
        #pragma unroll
        for (int w = 0; w < 16; w++) {
            qq += qp[w * 32 + t];
            ns += np[w * 32 + t];
        }
        out[b0 + t] = qq * ns;
    }
}

extern "C" void kernel_launch(void* const* d_in, const int* in_sizes, int n_in,
                              void* d_out, int out_size) {
    const float* X   = (const float*)d_in[0];
    const float* rho = (const float*)d_in[1];
    float* out = (float*)d_out;

    cudaFuncSetAttribute(qmd_mma, cudaFuncAttributeMaxDynamicSharedMemorySize, SMEM_TOTAL);
    qmd_mma<<<out_size / TILE_M, NTHREADS, SMEM_TOTAL>>>(X, rho, out);
}